// round 16
// baseline (speedup 1.0000x reference)
#include <cuda_runtime.h>

// cost_volumn: out[n,y,x, i*9+j] = (1/128) * sum_c f1[n,y,x,c] * f2[n, y+i-4, x+j-4, c]
// f1,f2: [8,128,256,128] f32 NHWC; out: [8,128,256,81] f32. Zero padding outside.
//
// Warp-specialized pipeline:
//   warps 0-17 : consumers — R6-proven pixel-major dot4 compute (register-window),
//                pure LDS+FMA instruction stream, no staging work at all.
//   warps 18-19: producers — cp.async.cg 16B copies global->swizzled smem,
//                double-buffered chunks of CC=8 channels.
// Sync: mbarriers only. full[b] (count=64, cp.async.mbarrier.arrive.noinc from each
// producer thread), empty[b] (count=18, lane0 of each consumer warp arrives).

#define DN 8
#define DH 128
#define DW 256
#define DC 128
#define RAD 4
#define NDX 9
#define NOFF 81

constexpr int YB      = 2;
constexpr int CC      = 8;               // channels per chunk (2 float4 quads)
constexpr int NCH     = DC / CC;         // 16 chunks
constexpr int PX      = 8;
constexpr int NCWARPS = 18;              // consumer warps
constexpr int THREADS = (NCWARPS + 2) * 32;   // 640
constexpr int XCOLS   = DW + 2 * RAD;    // 264
constexpr int YROWS   = YB + 2 * RAD;    // 10

// Buffer geometry in 16B chunks: [f2 quad0 | f2 quad1 | f1 quad0 | f1 quad1]
constexpr int F2PLANE   = YROWS * XCOLS;              // 2640
constexpr int F1PLANE   = YB * DW;                    // 512
constexpr int BUFCHUNKS = 2 * F2PLANE + 2 * F1PLANE;  // 6304
constexpr int BUFBYTES  = BUFCHUNKS * 16;             // 100,864
constexpr int TOTITEMS  = BUFCHUNKS;                  // cp.async items per chunk
constexpr int SMEM_BYTES = 2 * BUFBYTES + 64;         // + mbarriers

// XOR swizzle on 16B-chunk index (R6-proven): conflict-free for stride-8 windows.
__device__ __forceinline__ int swz(int x) {
    return (x & ~7) | ((x ^ (x >> 3)) & 7);
}

extern __shared__ float smem[];

__device__ __forceinline__ void cp16(unsigned dst, const void* src, int srcsize) {
    asm volatile("cp.async.cg.shared.global [%0], [%1], 16, %2;\n"
                 :: "r"(dst), "l"(src), "r"(srcsize));
}
__device__ __forceinline__ float dot4(float4 a, float4 b, float acc) {
    acc = fmaf(a.x, b.x, acc);
    acc = fmaf(a.y, b.y, acc);
    acc = fmaf(a.z, b.z, acc);
    acc = fmaf(a.w, b.w, acc);
    return acc;
}
__device__ __forceinline__ void mbar_wait(unsigned mb, unsigned ph) {
    unsigned done;
    asm volatile(
        "{\n\t.reg .pred p;\n\t"
        "mbarrier.try_wait.parity.acquire.cta.shared::cta.b64 p, [%1], %2;\n\t"
        "selp.b32 %0, 1, 0, p;\n\t}"
        : "=r"(done) : "r"(mb), "r"(ph) : "memory");
    if (!done) {
        asm volatile(
            "{\n\t.reg .pred P1;\n\t"
            "W_%=:\n\t"
            "mbarrier.try_wait.parity.acquire.cta.shared::cta.b64 P1, [%0], %1, 0x989680;\n\t"
            "@P1 bra.uni D_%=;\n\t"
            "bra.uni W_%=;\n\t"
            "D_%=:\n\t}"
            :: "r"(mb), "r"(ph) : "memory");
    }
}

__global__ __launch_bounds__(THREADS, 1)
void costvol_kernel(const float* __restrict__ f1,
                    const float* __restrict__ f2,
                    float* __restrict__ out)
{
    const int y0  = blockIdx.x * YB;
    const int n   = blockIdx.y;
    const int tid = threadIdx.x;
    const int w   = tid >> 5;

    const unsigned smem_u = (unsigned)__cvta_generic_to_shared(smem);
    const unsigned full_u  = smem_u + 2 * BUFBYTES;        // full[0], full[1]
    const unsigned empty_u = full_u + 16;                  // empty[0], empty[1]

    if (tid == 0) {
        asm volatile("mbarrier.init.shared.b64 [%0], 64;" :: "r"(full_u)      : "memory");
        asm volatile("mbarrier.init.shared.b64 [%0], 64;" :: "r"(full_u + 8)  : "memory");
        asm volatile("mbarrier.init.shared.b64 [%0], %1;" :: "r"(empty_u),     "r"(NCWARPS) : "memory");
        asm volatile("mbarrier.init.shared.b64 [%0], %1;" :: "r"(empty_u + 8), "r"(NCWARPS) : "memory");
        asm volatile("fence.proxy.async.shared::cta;" ::: "memory");
    }
    __syncthreads();

    const int rowPix = (n * DH + y0) * DW;

    if (w >= NCWARPS) {
        // ================= PRODUCER (warps 18-19, 64 threads) =================
        const int ptid = tid - NCWARPS * 32;      // 0..63
        const int q    = ptid & 1;                // channel quad (fixed per thread)
        const int q4   = q * 4;
        const int u0   = ptid >> 1;               // 0..31 (< XCOLS)

        #pragma unroll 1
        for (int k = 0; k < NCH; ++k) {
            if (k >= 2) mbar_wait(empty_u + (k & 1) * 8, (unsigned)(((k - 2) >> 1) & 1));

            const unsigned bbase = smem_u + (unsigned)(k & 1) * BUFBYTES;
            const int cofs = k * CC + q4;
            int t = ptid, row = 0, xcol = u0;
            #pragma unroll 1
            while (t < TOTITEMS) {
                const float* src;
                int sz, dstc;
                if (row < YROWS) {
                    const int y2 = y0 + row - RAD;
                    const int x2 = xcol - RAD;
                    const bool ok = ((unsigned)y2 < DH) & ((unsigned)x2 < DW);
                    src = f2 + (size_t)((n * DH + (ok ? y2 : 0)) * DW + (ok ? x2 : 0)) * DC + cofs;
                    sz  = ok ? 16 : 0;
                    dstc = q * F2PLANE + row * XCOLS + swz(xcol);
                } else {
                    const int v  = (row - YROWS) * XCOLS + xcol;   // 0..511
                    const int x  = v & (DW - 1);
                    const int r2 = v >> 8;
                    src = f1 + (size_t)(rowPix + r2 * DW + x) * DC + cofs;
                    sz  = 16;
                    dstc = 2 * F2PLANE + q * F1PLANE + r2 * DW + swz(x);
                }
                cp16(bbase + (unsigned)dstc * 16u, src, sz);
                t += 64;
                xcol += 32;
                if (xcol >= XCOLS) { xcol -= XCOLS; ++row; }
            }
            // arrive on full[k&1] when this thread's cp.asyncs complete
            asm volatile("cp.async.mbarrier.arrive.noinc.shared.b64 [%0];"
                         :: "r"(full_u + (k & 1) * 8) : "memory");
        }
    } else {
        // ================= CONSUMER (warps 0-17) =================
        const int r = w / NDX;                 // output row in block (0..1)
        const int i = w % NDX;                 // dy 0..8
        const int g = tid & 31;                // x-group: pixels 8g..8g+7
        const int wrow = r + i;                // f2 tile row (0..9)

        float acc[NDX][PX];
        #pragma unroll
        for (int a = 0; a < NDX; ++a)
            #pragma unroll
            for (int b = 0; b < PX; ++b) acc[a][b] = 0.f;

        #pragma unroll 1
        for (int k = 0; k < NCH; ++k) {
            mbar_wait(full_u + (k & 1) * 8, (unsigned)((k >> 1) & 1));

            const char* bb = (const char*)smem + (size_t)(k & 1) * BUFBYTES;
            #pragma unroll
            for (int q = 0; q < 2; ++q) {
                const float* F1p = (const float*)bb
                                 + (size_t)(2 * F2PLANE + q * F1PLANE + r * DW) * 4;
                const float* Wp  = (const float*)bb
                                 + (size_t)(q * F2PLANE + wrow * XCOLS) * 4;
                #pragma unroll
                for (int h = 0; h < 2; ++h) {
                    const int xb = 8 * g + 4 * h;       // first pixel of this half
                    float4 a4[4];
                    #pragma unroll
                    for (int p = 0; p < 4; ++p)
                        a4[p] = *reinterpret_cast<const float4*>(F1p + swz(xb + p) * 4);
                    #pragma unroll
                    for (int kk = 0; kk < 12; ++kk) {
                        const float4 w4 =
                            *reinterpret_cast<const float4*>(Wp + swz(xb + kk) * 4);
                        const int pmin = (kk - 8) > 0 ? (kk - 8) : 0;
                        const int pmax = kk < 3 ? kk : 3;
                        #pragma unroll
                        for (int p = 0; p < 4; ++p)
                            if (p >= pmin && p <= pmax)
                                acc[kk - p][4 * h + p] =
                                    dot4(a4[p], w4, acc[kk - p][4 * h + p]);
                    }
                }
            }
            if (g == 0)
                asm volatile("mbarrier.arrive.shared.b64 _, [%0];"
                             :: "r"(empty_u + (k & 1) * 8) : "memory");
        }

        // ---- epilogue: contiguous per-block output region ----
        const float inv = 1.0f / (float)DC;
        const int pixBase = rowPix + r * DW + g * PX;
        #pragma unroll
        for (int p = 0; p < PX; ++p) {
            const int ob = (pixBase + p) * NOFF + i * NDX;
            #pragma unroll
            for (int dx = 0; dx < NDX; ++dx)
                out[ob + dx] = acc[dx][p] * inv;
        }
    }
}

extern "C" void kernel_launch(void* const* d_in, const int* in_sizes, int n_in,
                              void* d_out, int out_size)
{
    const float* f1 = (const float*)d_in[0];
    const float* f2 = (const float*)d_in[1];
    float* out      = (float*)d_out;

    cudaFuncSetAttribute(costvol_kernel,
                         cudaFuncAttributeMaxDynamicSharedMemorySize, SMEM_BYTES);
    dim3 grid(DH / YB, DN);  // y fastest -> adjacent blocks share f2 halo in L2
    costvol_kernel<<<grid, THREADS, SMEM_BYTES>>>(f1, f2, out);
}

// round 17
// speedup vs baseline: 1.2587x; 1.2587x over previous
#include <cuda_runtime.h>

// cost_volumn: out[n,y,x, i*9+j] = (1/128) * sum_c f1[n,y,x,c] * f2[n, y+i-4, x+j-4, c]
// f1,f2: [8,128,256,128] f32 NHWC; out: [8,128,256,81] f32. Zero padding outside.
//
// R4 champion skeleton (CC=16 serial stage/sync/compute, channel-major swizzled smem,
// register-window FMA) with the compute inner loop converted to packed fma.rn.f32x2
// for even dx offsets (pixel-paired accumulators); odd dx stays scalar FFMA.

#define DN 8
#define DH 128
#define DW 256
#define DC 128
#define RAD 4
#define NDX 9
#define NOFF 81

constexpr int YB      = 2;             // output rows per block
constexpr int CC      = 16;            // channels per smem chunk
constexpr int NCH     = DC / CC;       // 8 chunks
constexpr int PX      = 8;             // pixels per thread
constexpr int THREADS = 576;           // 18 warps; warp=(row,dy), lane=x-group
constexpr int XCOLS   = DW + 2 * RAD;  // 264
constexpr int YROWS   = YB + 2 * RAD;  // 10 f2 rows per block
constexpr int ROWLEN  = 276;           // padded row stride (floats)
constexpr int F2ROWS  = YROWS * CC;    // 160
constexpr int F1ROWS  = YB * CC;       // 32
constexpr int SMEM_BYTES = (F2ROWS + F1ROWS) * ROWLEN * 4;  // 211,968 B

constexpr int F2ITEMS  = YROWS * XCOLS * 4;      // 10560 float4 staging items
constexpr int TOTITEMS = F2ITEMS + YB * DW * 4;  // 12608

// XOR swizzle on 16B chunks (proven): conflict-free window LDS + STS scatter.
__device__ __forceinline__ int swzidx(int xc) {
    int j = xc >> 2;
    j ^= (j >> 3) & 7;
    return (j << 2) | (xc & 3);
}
__device__ __forceinline__ int swzchunk4(int j) {
    return (j ^ ((j >> 3) & 7)) << 2;
}

typedef unsigned long long ull;

// Pack two f32 regs into a 64-bit pair (ptxas coalesces aligned pairs to an alias).
__device__ __forceinline__ ull pk(float lo, float hi) {
    ull r;
    asm("mov.b64 %0, {%1, %2};" : "=l"(r) : "f"(lo), "f"(hi));
    return r;
}
__device__ __forceinline__ void unpk(float& lo, float& hi, ull v) {
    asm("mov.b64 {%0, %1}, %2;" : "=f"(lo), "=f"(hi) : "l"(v));
}
// Packed dual FMA: d = a*b + c elementwise on f32x2.
__device__ __forceinline__ ull ffma2(ull a, ull b, ull c) {
    ull d;
    asm("fma.rn.f32x2 %0, %1, %2, %3;" : "=l"(d) : "l"(a), "l"(b), "l"(c));
    return d;
}

extern __shared__ float smem[];

__global__ __launch_bounds__(THREADS, 1)
void costvol_kernel(const float* __restrict__ f1,
                    const float* __restrict__ f2,
                    float* __restrict__ out)
{
    const int y0  = blockIdx.x * YB;   // first output row of this block
    const int n   = blockIdx.y;        // batch
    const int tid = threadIdx.x;
    const int w   = tid >> 5;          // warp 0..17
    const int r   = w / NDX;           // output row within block (0..1)
    const int i   = w % NDX;           // dy index 0..8
    const int g   = tid & 31;          // x-group: pixels 8g..8g+7

    float* sF2 = smem;                           // [YROWS*CC][ROWLEN]
    float* sF1 = smem + F2ROWS * ROWLEN;         // [YB*CC][ROWLEN]

    const int pw0 = swzchunk4(2 * g + 0);
    const int pw1 = swzchunk4(2 * g + 1);
    const int pw2 = swzchunk4(2 * g + 2);
    const int pw3 = swzchunk4(2 * g + 3);

    // Accumulators: even dx (0,2,4,6,8) as pixel-paired f32x2; odd dx scalar.
    ull   acc2[5][4];                  // [dx/2][pixel-pair]  (lo=px 2p2, hi=px 2p2+1)
    float acc1[4][PX];                 // [(dx-1)/2][pixel]
    #pragma unroll
    for (int a = 0; a < 5; ++a)
        #pragma unroll
        for (int b = 0; b < 4; ++b) acc2[a][b] = 0ULL;   // bits of (0.f, 0.f)
    #pragma unroll
    for (int a = 0; a < 4; ++a)
        #pragma unroll
        for (int b = 0; b < PX; ++b) acc1[a][b] = 0.f;

    const int rowPix = (n * DH + y0) * DW;  // pixel index of (n, y0, 0)

    for (int cc = 0; cc < NCH; ++cc) {
        __syncthreads();
        // ------------ stage chunk cc (CC=16 channels), R4-proven ---------------
        const int cofs = cc * CC;
        for (int t = tid; t < TOTITEMS; t += THREADS) {
            if (t < F2ITEMS) {
                const int q    = t & 3;
                const unsigned u = (unsigned)t >> 2;
                const int xcol = (int)(u % (unsigned)XCOLS);
                const int row  = (int)(u / (unsigned)XCOLS);
                const int y2 = y0 + row - RAD;
                const int x2 = xcol - RAD;
                float4 v = make_float4(0.f, 0.f, 0.f, 0.f);
                if (((unsigned)y2 < DH) & ((unsigned)x2 < DW)) {
                    v = *reinterpret_cast<const float4*>(
                        f2 + (size_t)((n * DH + y2) * DW + x2) * DC + cofs + q * 4);
                }
                float* dst = sF2 + (row * CC + q * 4) * ROWLEN + swzidx(xcol);
                dst[0]          = v.x;
                dst[ROWLEN]     = v.y;
                dst[2 * ROWLEN] = v.z;
                dst[3 * ROWLEN] = v.w;
            } else {
                const int t2 = t - F2ITEMS;
                const int q  = t2 & 3;
                const int u  = t2 >> 2;
                const int x  = u & (DW - 1);
                const int r2 = u >> 8;
                const float4 v = *reinterpret_cast<const float4*>(
                    f1 + (size_t)(rowPix + r2 * DW + x) * DC + cofs + q * 4);
                float* dst = sF1 + (r2 * CC + q * 4) * ROWLEN + swzidx(x);
                dst[0]          = v.x;
                dst[ROWLEN]     = v.y;
                dst[2 * ROWLEN] = v.z;
                dst[3 * ROWLEN] = v.w;
            }
        }
        __syncthreads();
        // ------------ compute: 16 channels, mixed f32x2 / scalar FMA ------------
        #pragma unroll
        for (int c = 0; c < CC; ++c) {
            const float* r1 = sF1 + (r * CC + c) * ROWLEN;
            const float4 a0 = *reinterpret_cast<const float4*>(r1 + pw0);
            const float4 a1 = *reinterpret_cast<const float4*>(r1 + pw1);
            const float* r2 = sF2 + ((r + i) * CC + c) * ROWLEN;
            const float4 w0 = *reinterpret_cast<const float4*>(r2 + pw0);
            const float4 w1 = *reinterpret_cast<const float4*>(r2 + pw1);
            const float4 w2 = *reinterpret_cast<const float4*>(r2 + pw2);
            const float4 w3 = *reinterpret_cast<const float4*>(r2 + pw3);
            const float a[PX]  = {a0.x, a0.y, a0.z, a0.w, a1.x, a1.y, a1.z, a1.w};
            const float wv[16] = {w0.x, w0.y, w0.z, w0.w, w1.x, w1.y, w1.z, w1.w,
                                  w2.x, w2.y, w2.z, w2.w, w3.x, w3.y, w3.z, w3.w};
            // aligned pairs (alias the float4 register pairs; no data movement)
            const ull a2[4] = { pk(a[0], a[1]), pk(a[2], a[3]),
                                pk(a[4], a[5]), pk(a[6], a[7]) };
            const ull wp[8] = { pk(wv[0],  wv[1]),  pk(wv[2],  wv[3]),
                                pk(wv[4],  wv[5]),  pk(wv[6],  wv[7]),
                                pk(wv[8],  wv[9]),  pk(wv[10], wv[11]),
                                pk(wv[12], wv[13]), pk(wv[14], wv[15]) };
            // even dx = 2*dxp: w-pair starts at even offset 2*p2 + 2*dxp
            #pragma unroll
            for (int dxp = 0; dxp < 5; ++dxp)
                #pragma unroll
                for (int p2 = 0; p2 < 4; ++p2)
                    acc2[dxp][p2] = ffma2(a2[p2], wp[p2 + dxp], acc2[dxp][p2]);
            // odd dx = 2*dxo+1: scalar
            #pragma unroll
            for (int dxo = 0; dxo < 4; ++dxo)
                #pragma unroll
                for (int p = 0; p < PX; ++p)
                    acc1[dxo][p] = fmaf(a[p], wv[p + 2 * dxo + 1], acc1[dxo][p]);
        }
    }

    // ------------ epilogue: unpack pairs, contiguous per-block region ----------
    float accF[NDX][PX];
    #pragma unroll
    for (int dxp = 0; dxp < 5; ++dxp)
        #pragma unroll
        for (int p2 = 0; p2 < 4; ++p2)
            unpk(accF[2 * dxp][2 * p2], accF[2 * dxp][2 * p2 + 1], acc2[dxp][p2]);
    #pragma unroll
    for (int dxo = 0; dxo < 4; ++dxo)
        #pragma unroll
        for (int p = 0; p < PX; ++p)
            accF[2 * dxo + 1][p] = acc1[dxo][p];

    const float inv = 1.0f / (float)DC;
    const int pixBase = rowPix + r * DW + g * PX;
    #pragma unroll
    for (int p = 0; p < PX; ++p) {
        const int ob = (pixBase + p) * NOFF + i * NDX;
        #pragma unroll
        for (int dx = 0; dx < NDX; ++dx)
            out[ob + dx] = accF[dx][p] * inv;
    }
}

extern "C" void kernel_launch(void* const* d_in, const int* in_sizes, int n_in,
                              void* d_out, int out_size)
{
    const float* f1 = (const float*)d_in[0];
    const float* f2 = (const float*)d_in[1];
    float* out      = (float*)d_out;

    cudaFuncSetAttribute(costvol_kernel,
                         cudaFuncAttributeMaxDynamicSharedMemorySize, SMEM_BYTES);
    dim3 grid(DH / YB, DN);  // y fastest -> adjacent blocks share f2 halo in L2
    costvol_kernel<<<grid, THREADS, SMEM_BYTES>>>(f1, f2, out);
}